// round 17
// baseline (speedup 1.0000x reference)
#include <cuda_runtime.h>
#include <math.h>

#define DD 256
#define HH 512
#define BB 128
typedef unsigned long long ull;

__device__ __forceinline__ ull packf2(float lo, float hi) {
    return ((ull)__float_as_uint(hi) << 32) | (ull)__float_as_uint(lo);
}
__device__ __forceinline__ void ffma2(ull& d, ull a, ull b) {
    asm("fma.rn.f32x2 %0, %1, %2, %0;" : "+l"(d) : "l"(a), "l"(b));
}

// Vectorized masked weights, fp32 (mu,lv) pairs, degree-sorted units.
__device__ ulonglong2 gW0v[256 * 256];  // [j][v]: units 2v,2v+1 ; ncol(j) -> a0
__device__ ulonglong2 gW1v[512 * 256];  // [p][v]: h0[p] -> a1
__device__ ulonglong2 gWov[512 * 128];  // [g][v]: cols 2v,2v+1 ; h1[g] -> aout
__device__ float g_recS[256 * 40];      // chain records (identical to R14)
__device__ float g_recW[4 * 68];

__device__ __forceinline__ int permf(int p) {
    if (p < 3) return (p == 0) ? 0 : ((p == 1) ? 255 : 510);
    if (p < 6) { int q = p - 3; return (q == 0) ? 1 : ((q == 1) ? 256 : 511); }
    int d = 3 + ((p - 6) >> 1);
    return (((p - 6) & 1) == 0) ? (d - 1) : (d + 254);
}
__device__ __forceinline__ int degf(int p) {
    if (p < 3) return 1;
    if (p < 6) return 2;
    return 3 + ((p - 6) >> 1);
}
__device__ __forceinline__ int Pof(int k) {
    if (k <= 0) return 0;
    if (k == 1) return 3;
    int v = 2 * k + 2;
    return v > HH ? HH : v;
}
__device__ __forceinline__ float elu1(float a) {
    float e = __expf(a) - 1.f;
    return a > 0.f ? a : e;
}

__global__ void setup_kernel(
    const float* __restrict__ W0m, const float* __restrict__ W1m, const float* __restrict__ Wom,
    const float* __restrict__ b0m, const float* __restrict__ b1m,
    const float* __restrict__ W0l, const float* __restrict__ W1l, const float* __restrict__ Wol,
    const float* __restrict__ b0l, const float* __restrict__ b1l,
    const float* __restrict__ bom, const float* __restrict__ bol)
{
    int tid = blockIdx.x * blockDim.x + threadIdx.x;
    int stride = gridDim.x * blockDim.x;

    for (int idx = tid; idx < 256 * 256; idx += stride) {
        int j = idx >> 8, v = idx & 255;
        ulonglong2 w;
        int u0 = 2 * v, u1 = 2 * v + 1;
        float m0 = (degf(u0) >= j + 1) ? 1.f : 0.f;
        float m1 = (degf(u1) >= j + 1) ? 1.f : 0.f;
        int o0 = permf(u0), o1 = permf(u1);
        w.x = packf2(m0 * W0m[o0 * DD + j], m0 * W0l[o0 * DD + j]);
        w.y = packf2(m1 * W0m[o1 * DD + j], m1 * W0l[o1 * DD + j]);
        gW0v[idx] = w;
    }
    for (int idx = tid; idx < 512 * 256; idx += stride) {
        int p = idx >> 8, v = idx & 255;
        int op = permf(p), dp = degf(p);
        ulonglong2 w;
        int g0 = 2 * v, g1 = 2 * v + 1;
        float m0 = (degf(g0) >= dp) ? 1.f : 0.f;
        float m1 = (degf(g1) >= dp) ? 1.f : 0.f;
        int o0 = permf(g0), o1 = permf(g1);
        w.x = packf2(m0 * W1m[o0 * HH + op], m0 * W1l[o0 * HH + op]);
        w.y = packf2(m1 * W1m[o1 * HH + op], m1 * W1l[o1 * HH + op]);
        gW1v[idx] = w;
    }
    for (int idx = tid; idx < 512 * 128; idx += stride) {
        int g = idx >> 7, v = idx & 127;
        int og = permf(g), dg = degf(g);
        ulonglong2 w;
        int c0 = 2 * v, c1 = 2 * v + 1;
        float m0 = (c0 >= dg) ? 1.f : 0.f;
        float m1 = (c1 >= dg) ? 1.f : 0.f;
        w.x = packf2(m0 * Wom[c0 * HH + og], m0 * Wol[c0 * HH + og]);
        w.y = packf2(m1 * Wom[c1 * HH + og], m1 * Wol[c1 * HH + og]);
        gWov[idx] = w;
    }
    for (int i = tid; i < 256; i += stride) {
        int cB = Pof(i - 1), cc = Pof(i) - cB;
        int pB = Pof(i - 2), cp = Pof(i - 1) - pB;
        {
            float* r = g_recS + i * 40;
            for (int k = 0; k < 40; k++) r[k] = 0.f;
            int c2 = cc < 2 ? cc : 2, p2 = cp < 2 ? cp : 2;
            for (int s = 0; s < c2; s++) {
                int p = permf(cB + s);
                if (i >= 1) { r[0 + 2 * s] = W0m[p * DD + (i - 1)]; r[1 + 2 * s] = W0l[p * DD + (i - 1)]; }
                r[4 + 2 * s] = b0m[p];  r[5 + 2 * s] = b0l[p];
                r[8 + 2 * s] = b1m[p];  r[9 + 2 * s] = b1l[p];
                r[32 + 2 * s] = Wom[i * HH + p]; r[33 + 2 * s] = Wol[i * HH + p];
            }
            for (int sp = 0; sp < p2; sp++) {
                int pp = permf(pB + sp);
                r[28 + 2 * sp] = Wom[i * HH + pp]; r[29 + 2 * sp] = Wol[i * HH + pp];
                for (int sc = 0; sc < c2; sc++) {
                    int g = permf(cB + sc);
                    r[12 + sp * 4 + 2 * sc] = W1m[g * HH + pp];
                    r[13 + sp * 4 + 2 * sc] = W1l[g * HH + pp];
                }
            }
            for (int sp = 0; sp < c2; sp++)
                for (int sc = 0; sc < c2; sc++) {
                    int pp = permf(cB + sp), g = permf(cB + sc);
                    r[20 + sp * 4 + 2 * sc] = W1m[g * HH + pp];
                    r[21 + sp * 4 + 2 * sc] = W1l[g * HH + pp];
                }
            r[36] = bom[i]; r[37] = bol[i];
        }
        if (i < 4) {
            float* r = g_recW + i * 68;
            for (int k = 0; k < 68; k++) r[k] = 0.f;
            for (int s = 0; s < cc; s++) {
                int p = permf(cB + s);
                if (i >= 1) { r[0 + 2 * s] = W0m[p * DD + (i - 1)]; r[1 + 2 * s] = W0l[p * DD + (i - 1)]; }
                r[6 + 2 * s] = b0m[p];  r[7 + 2 * s] = b0l[p];
                r[12 + 2 * s] = b1m[p]; r[13 + 2 * s] = b1l[p];
                r[60 + 2 * s] = Wom[i * HH + p]; r[61 + 2 * s] = Wol[i * HH + p];
            }
            for (int sp = 0; sp < cp; sp++) {
                int pp = permf(pB + sp);
                r[54 + 2 * sp] = Wom[i * HH + pp]; r[55 + 2 * sp] = Wol[i * HH + pp];
                for (int sc = 0; sc < cc; sc++) {
                    int g = permf(cB + sc);
                    r[18 + sp * 6 + 2 * sc] = W1m[g * HH + pp];
                    r[19 + sp * 6 + 2 * sc] = W1l[g * HH + pp];
                }
            }
            for (int sp = 0; sp < cc; sp++)
                for (int sc = 0; sc < cc; sc++) {
                    int pp = permf(cB + sp), g = permf(cB + sc);
                    r[36 + sp * 6 + 2 * sc] = W1m[g * HH + pp];
                    r[37 + sp * 6 + 2 * sc] = W1l[g * HH + pp];
                }
            r[66] = bom[i]; r[67] = bol[i];
        }
    }
}

// One warp per CTA, 128 CTAs. Lane L owns interleaved unit-pairs v = L + 32q.
__global__ __launch_bounds__(32, 1) void made_kernel(
    const float* __restrict__ x, float* __restrict__ out)
{
    __shared__ __align__(16) ull a0s[512], a1s[512], aos[256];
    __shared__ __align__(16) float xs[256], recw[272], recbuf[80];
    __shared__ __align__(16) float pr[16], pu[16];

    const int L = threadIdx.x;
    const int n = L;   // chain lane id (only 0,1 used)
    const int b = blockIdx.x;

    for (int k = L; k < 512; k += 32) { a0s[k] = 0ull; a1s[k] = 0ull; }
    for (int k = L; k < 256; k += 32) { aos[k] = 0ull; xs[k] = x[b * DD + k]; }
    for (int k = L; k < 272; k += 32) recw[k] = g_recW[k];
    if (L < 16) { pr[L] = 0.f; pu[L] = 0.f; }
    __syncwarp();

    ulonglong2* const a0v = (ulonglong2*)a0s;
    ulonglong2* const a1v = (ulonglong2*)a1s;
    ulonglong2* const aov = (ulonglong2*)aos;
    ull* const prU = (ull*)pr;
    ull* const puU = (ull*)pu;
    float* const outb = out + b * DD;

    // prefetch step-0 scatter weights (broadcasts are zero; values just need to be finite)
    ulonglong2 pf0[8], pf1[2][8], pfo[2][4];
#pragma unroll
    for (int q = 0; q < 8; q++) {
        pf0[q] = gW0v[L + 32 * q];
        pf1[0][q] = gW1v[L + 32 * q];
        pf1[1][q] = gW1v[256 + L + 32 * q];
    }
#pragma unroll
    for (int q = 0; q < 4; q++) {
        pfo[0][q] = gWov[L + 32 * q];
        pfo[1][q] = gWov[128 + L + 32 * q];
    }

    ull ncP = 0, h0b0 = 0, h0b1 = 0, h0b2 = 0, h1b0 = 0, h1b1 = 0, h1b2 = 0;
    float nc = 0.f, lvs = 0.f;
    float h0p0 = 0.f, h0p1 = 0.f, h0p2 = 0.f;
    float h1p0 = 0.f, h1p1 = 0.f, h1p2 = 0.f;

#pragma unroll 1
    for (int i = 0; i < DD; i++) {
        const int cB = Pof(i - 1), pB = Pof(i - 2), cBn = Pof(i);

        // ---- stage chain inputs (pre-scatter) ----
        if (L == 0) { prU[0] = a0s[cB]; prU[1] = a1s[cB]; }
        else if (L == 1) { int c = cB + 1 > 511 ? 511 : cB + 1; prU[2] = a0s[c]; prU[3] = a1s[c]; }
        else if (L == 2) { int c = cB + 2 > 511 ? 511 : cB + 2; prU[4] = a0s[c]; prU[5] = a1s[c]; }
        else if (L == 3) { prU[6] = aos[i]; }
        __syncwarp();

        // ---- scatter (adds step i-1's ncol / h0 / h1) ----
#pragma unroll
        for (int q = 0; q < 8; q++) if (64 * q + 64 > cB) {
            ulonglong2 a = a0v[L + 32 * q];
            ffma2(a.x, ncP, pf0[q].x); ffma2(a.y, ncP, pf0[q].y);
            a0v[L + 32 * q] = a;
        }
#pragma unroll
        for (int q = 0; q < 8; q++) if (64 * q + 64 > pB) {
            ulonglong2 a = a1v[L + 32 * q];
            ffma2(a.x, h0b0, pf1[0][q].x); ffma2(a.y, h0b0, pf1[0][q].y);
            ffma2(a.x, h0b1, pf1[1][q].x); ffma2(a.y, h0b1, pf1[1][q].y);
            a1v[L + 32 * q] = a;
        }
#pragma unroll
        for (int q = 0; q < 4; q++) if (64 * q + 64 > i - 1) {
            ulonglong2 a = aov[L + 32 * q];
            ffma2(a.x, h1b0, pfo[0][q].x); ffma2(a.y, h1b0, pfo[0][q].y);
            ffma2(a.x, h1b1, pfo[1][q].x); ffma2(a.y, h1b1, pfo[1][q].y);
            aov[L + 32 * q] = a;
        }
        if (i == 2 || i == 3) {   // warm slot-2 (3-unit degree groups)
            const ulonglong2* w1r = gW1v + (pB + 2) * 256;
            const ulonglong2* wor = gWov + (pB + 2) * 128;
#pragma unroll
            for (int q = 0; q < 8; q++) {
                ulonglong2 w = w1r[L + 32 * q];
                ulonglong2 a = a1v[L + 32 * q];
                ffma2(a.x, h0b2, w.x); ffma2(a.y, h0b2, w.y);
                a1v[L + 32 * q] = a;
            }
#pragma unroll
            for (int q = 0; q < 4; q++) {
                ulonglong2 w = wor[L + 32 * q];
                ulonglong2 a = aov[L + 32 * q];
                ffma2(a.x, h1b2, w.x); ffma2(a.y, h1b2, w.y);
                aov[L + 32 * q] = a;
            }
        }

        // ---- prefetch weights + record for step i+1 ----
        if (i < 255) {
            const ulonglong2* w0r = gW0v + i * 256;          // ncol(i) row
            const ulonglong2* r0 = gW1v + cB * 256;          // S(i) rows
            const ulonglong2* r1 = gW1v + (cB + 1 > 511 ? 511 : cB + 1) * 256;
            const ulonglong2* o0 = gWov + cB * 128;
            const ulonglong2* o1 = gWov + (cB + 1 > 511 ? 511 : cB + 1) * 128;
#pragma unroll
            for (int q = 0; q < 8; q++) {
                if (64 * q + 64 > cBn) pf0[q] = w0r[L + 32 * q];
                if (64 * q + 64 > cB) { pf1[0][q] = r0[L + 32 * q]; pf1[1][q] = r1[L + 32 * q]; }
            }
#pragma unroll
            for (int q = 0; q < 4; q++) if (64 * q + 64 > i) {
                pfo[0][q] = o0[L + 32 * q]; pfo[1][q] = o1[L + 32 * q];
            }
            if (L < 20 && i + 1 >= 4) {
                float2 v = *(const float2*)&g_recS[(i + 1) * 40 + 2 * L];
                *(float2*)&recbuf[((i + 1) & 1) * 40 + 2 * L] = v;
            }
        }

        // ---- chain on lanes 0,1 (net-split, R14 math) ----
        if (L < 2) {
            const float xi = xs[i];
            float h0c0, h0c1, h0c2 = 0.f, h1c0, h1c1, h1c2 = 0.f, m;
            if (i >= 4) {
                const float* r = recbuf + (i & 1) * 40 + n;
                h0c0 = elu1(pr[0 + n] + nc * r[0] + r[4]);
                h0c1 = elu1(pr[4 + n] + nc * r[2] + r[6]);
                float a0 = pr[2 + n] + r[8];
                a0 = fmaf(h0p0, r[12], a0); a0 = fmaf(h0p1, r[16], a0);
                a0 = fmaf(h0c0, r[20], a0); a0 = fmaf(h0c1, r[24], a0);
                h1c0 = elu1(a0);
                float a1 = pr[6 + n] + r[10];
                a1 = fmaf(h0p0, r[14], a1); a1 = fmaf(h0p1, r[18], a1);
                a1 = fmaf(h0c0, r[22], a1); a1 = fmaf(h0c1, r[26], a1);
                h1c1 = elu1(a1);
                m = pr[12 + n] + r[36];
                m = fmaf(h1p0, r[28], m); m = fmaf(h1p1, r[30], m);
                m = fmaf(h1c0, r[32], m); m = fmaf(h1c1, r[34], m);
            } else {
                const float* r = recw + i * 68 + n;
                h0c0 = elu1(pr[0 + n] + nc * r[0] + r[6]);
                h0c1 = elu1(pr[4 + n] + nc * r[2] + r[8]);
                h0c2 = elu1(pr[8 + n] + nc * r[4] + r[10]);
                float a0 = pr[2 + n] + r[12];
                a0 = fmaf(h0p0, r[18], a0); a0 = fmaf(h0p1, r[24], a0); a0 = fmaf(h0p2, r[30], a0);
                a0 = fmaf(h0c0, r[36], a0); a0 = fmaf(h0c1, r[42], a0); a0 = fmaf(h0c2, r[48], a0);
                h1c0 = elu1(a0);
                float a1 = pr[6 + n] + r[14];
                a1 = fmaf(h0p0, r[20], a1); a1 = fmaf(h0p1, r[26], a1); a1 = fmaf(h0p2, r[32], a1);
                a1 = fmaf(h0c0, r[38], a1); a1 = fmaf(h0c1, r[44], a1); a1 = fmaf(h0c2, r[50], a1);
                h1c1 = elu1(a1);
                float a2 = pr[10 + n] + r[16];
                a2 = fmaf(h0p0, r[22], a2); a2 = fmaf(h0p1, r[28], a2); a2 = fmaf(h0p2, r[34], a2);
                a2 = fmaf(h0c0, r[40], a2); a2 = fmaf(h0c1, r[46], a2); a2 = fmaf(h0c2, r[52], a2);
                h1c2 = elu1(a2);
                m = pr[12 + n] + r[66];
                m = fmaf(h1p0, r[54], m); m = fmaf(h1p1, r[56], m); m = fmaf(h1p2, r[58], m);
                m = fmaf(h1c0, r[60], m); m = fmaf(h1c1, r[62], m); m = fmaf(h1c2, r[64], m);
            }
            const float other = __shfl_xor_sync(0x3u, m, 1);
            const float mu = (n == 0) ? m : other;
            const float lv = (n == 0) ? other : m;
            const float ls = 0.5f * lv;
            const float ncn = (xi - mu) * __expf(-ls);
            nc = ncn;
            if (n) lvs += ls;
            else   outb[i] = ncn;
            pu[n] = ncn;
            pu[2 + n] = h0c0; pu[4 + n] = h0c1;
            pu[6 + n] = h1c0; pu[8 + n] = h1c1;
            if (i < 4) { pu[10 + n] = h0c2; pu[12 + n] = h1c2; }
            h0p0 = h0c0; h0p1 = h0c1; h0p2 = h0c2;
            h1p0 = h1c0; h1p1 = h1c1; h1p2 = h1c2;
        }
        __syncwarp();

        // ---- pick up broadcasts for next step's scatter ----
        ncP = puU[0];
        h0b0 = puU[1]; h0b1 = puU[2];
        h1b0 = puU[3]; h1b1 = puU[4];
        if (i == 1 || i == 2) { h0b2 = puU[5]; h1b2 = puU[6]; }
        else { h0b2 = 0; h1b2 = 0; }
        __syncwarp();
    }

    if (L == 1) out[BB * DD + b] = lvs;
}

extern "C" void kernel_launch(void* const* d_in, const int* in_sizes, int n_in,
                              void* d_out, int out_size) {
    const float* xx   = (const float*)d_in[0];
    const float* muW0 = (const float*)d_in[1];
    const float* mub0 = (const float*)d_in[2];
    const float* muW1 = (const float*)d_in[3];
    const float* mub1 = (const float*)d_in[4];
    const float* muWo = (const float*)d_in[5];
    const float* mubo = (const float*)d_in[6];
    const float* lvW0 = (const float*)d_in[7];
    const float* lvb0 = (const float*)d_in[8];
    const float* lvW1 = (const float*)d_in[9];
    const float* lvb1 = (const float*)d_in[10];
    const float* lvWo = (const float*)d_in[11];
    const float* lvbo = (const float*)d_in[12];
    float* out = (float*)d_out;

    setup_kernel<<<512, 256>>>(muW0, muW1, muWo, mub0, mub1,
                               lvW0, lvW1, lvWo, lvb0, lvb1, mubo, lvbo);
    made_kernel<<<BB, 32>>>(xx, out);
}